// round 3
// baseline (speedup 1.0000x reference)
#include <cuda_runtime.h>
#include <cstdint>

// TangentInvariant: fused sphere-log + VN layer + Gram features + dense GEMM.
// B=16, S=8192 -> N=131072 tokens. C=32 (1 base + 31 tangent), D=3.
// feat = 31*16 = 496, OUT_CH = 128.
//
// One block = 64 tokens, 256 threads, grid = 2048.
// Phase 1: compute v[31][3], w[16][3], y[496] per token into smem (y stored
//          feature-major: ysm[f][64 tokens]).
// Phase 2: GEMM out[64,128] += y[64,496] * K[496,128] using packed
//          fma.rn.f32x2 (2 fp32 FMA per inst), K staged in 64-row chunks via
//          double-buffered cp.async (K is L2-resident: 248KB shared by all blocks).

#define NTHREADS 256

__device__ __forceinline__ unsigned smaddr(const void* p) {
    return (unsigned)__cvta_generic_to_shared(p);
}

__device__ __forceinline__ void cp16(unsigned dst, const float* src) {
    asm volatile("cp.async.cg.shared.global [%0], [%1], 16;\n" :: "r"(dst), "l"(src));
}

__global__ __launch_bounds__(NTHREADS, 1)
void tangent_kernel(const float* __restrict__ x,
                    const float* __restrict__ U0,
                    const float* __restrict__ W0,
                    const float* __restrict__ Kd,
                    const float* __restrict__ bias,
                    float* __restrict__ out)
{
    extern __shared__ float smem[];
    // Layout (floats):
    // [0, 31744)            ysm   : y feature-major  [496][64]
    // [31744, 39936)        kbuf0 : K chunk buffer 0 [64][128]
    // [39936, 56320)        R     : 16384-float region, temporally shared:
    //    phase 1:  xs[64*96] @R+0, vsm[64*31*3] @R+6144, wsm[64*16*3] @R+12096,
    //              Usm[496] @R+15168, Wsm[496] @R+15664
    //    phase 2:  kbuf1 [64][128] @R+0
    float* ysm   = smem;
    float* kbuf0 = smem + 31744;
    float* Rr    = smem + 39936;
    float* kbuf1 = Rr;
    float* xs    = Rr;
    float* vsm   = Rr + 6144;
    float* wsm   = Rr + 12096;
    float* Usm   = Rr + 15168;
    float* Wsm   = Rr + 15664;

    const int tid = threadIdx.x;

    // ---- prefetch K chunk 0 into kbuf0 (hidden under phase 1) ----
    {
        unsigned dst = smaddr(kbuf0);
        for (int g = tid; g < 2048; g += NTHREADS)   // 64*128 floats = 2048 f4
            cp16(dst + g * 16, Kd + g * 4);
        asm volatile("cp.async.commit_group;\n" ::: "memory");
    }

    // ---- load x tile (64 tokens * 96 floats) and U/W weights ----
    {
        const float4* src = (const float4*)(x + (size_t)blockIdx.x * (64 * 96));
        float4* dst = (float4*)xs;
        for (int g = tid; g < 1536; g += NTHREADS) dst[g] = src[g];
        for (int g = tid; g < 496; g += NTHREADS) { Usm[g] = U0[g]; Wsm[g] = W0[g]; }
    }
    __syncthreads();

    // ---- phase 1a: sphere log -> v  (64 tokens * 31 tangent vecs) ----
    for (int idx = tid; idx < 64 * 31; idx += NTHREADS) {
        int t = idx / 31;
        int j = idx - t * 31;
        const float* xt = xs + t * 96;
        float px = xt[0], py = xt[1], pz = xt[2];
        const float* q = xt + 3 + j * 3;
        float qx = q[0], qy = q[1], qz = q[2];
        float cs = px * qx + py * qy + pz * qz;
        cs = fminf(1.0f, fmaxf(-1.0f, cs));
        float th = acosf(cs);
        float fac = (th < 1e-6f) ? 1.0f : th / sinf(th);
        float* vo = vsm + t * 93 + j * 3;
        vo[0] = fac * (qx - cs * px);
        vo[1] = fac * (qy - cs * py);
        vo[2] = fac * (qz - cs * pz);
    }
    __syncthreads();

    // ---- phase 1b: VN layer -> w  (64 tokens * 16 outputs) ----
    for (int idx = tid; idx < 64 * 16; idx += NTHREADS) {
        int t = idx >> 4;
        int i = idx & 15;
        const float* vb = vsm + t * 93;
        const float* Ur = Usm + i * 31;
        const float* Wr = Wsm + i * 31;
        float kx = 0.f, ky = 0.f, kz = 0.f, qx = 0.f, qy = 0.f, qz = 0.f;
        #pragma unroll
        for (int j = 0; j < 31; ++j) {
            float u = Ur[j], w_ = Wr[j];
            float vx = vb[j * 3 + 0], vy = vb[j * 3 + 1], vz = vb[j * 3 + 2];
            kx += u * vx;  ky += u * vy;  kz += u * vz;
            qx += w_ * vx; qy += w_ * vy; qz += w_ * vz;
        }
        float sq = kx * kx + ky * ky + kz * kz + 2.2204460492503131e-16f;
        float dt = qx * kx + qy * ky + qz * kz;
        float r = 0.8f * fmaxf(-dt, 0.0f) / sq;   // 0.2*q + 0.8*(q + k*relu(-dot)/sq)
        float* wo = wsm + t * 48 + i * 3;
        wo[0] = qx + r * kx;
        wo[1] = qy + r * ky;
        wo[2] = qz + r * kz;
    }
    __syncthreads();

    // ---- phase 1c: Gram features y[f = i*16 + k] = v_i . w_k ----
    for (int idx = tid; idx < 64 * 496; idx += NTHREADS) {
        int t = idx & 63;
        int f = idx >> 6;
        int i = f >> 4;
        int kk = f & 15;
        const float* vv = vsm + t * 93 + i * 3;
        const float* ww = wsm + t * 48 + kk * 3;
        ysm[f * 64 + t] = vv[0] * ww[0] + vv[1] * ww[1] + vv[2] * ww[2];
    }
    __syncthreads();

    // ---- prefetch K chunk 1 into kbuf1 (overlays dead xs/vsm region) ----
    {
        unsigned dst = smaddr(kbuf1);
        const float* src = Kd + 64 * 128;
        for (int g = tid; g < 2048; g += NTHREADS)
            cp16(dst + g * 16, src + g * 4);
        asm volatile("cp.async.commit_group;\n" ::: "memory");
    }

    // ---- phase 2: GEMM out[64,128] = y[64,496] * K[496,128] ----
    // thread (tx=tid&31, ty=tid>>5): rows m = ty*8..ty*8+7, cols c = tx*4..tx*4+3
    // acc[mp][cc] packs output pair (m = ty*8+2mp, ty*8+2mp+1) at col tx*4+cc.
    const int tx = tid & 31, ty = tid >> 5;
    unsigned long long acc[4][4];
    #pragma unroll
    for (int a = 0; a < 4; ++a)
        #pragma unroll
        for (int b = 0; b < 4; ++b) acc[a][b] = 0ull;

    const unsigned ybase = smaddr(ysm) + (unsigned)ty * 32;
    const unsigned kb0 = smaddr(kbuf0) + (unsigned)tx * 16;
    const unsigned kb1 = smaddr(kbuf1) + (unsigned)tx * 16;

    #pragma unroll
    for (int c = 0; c < 8; ++c) {
        asm volatile("cp.async.wait_group 1;\n" ::: "memory");
        __syncthreads();
        const int len = (c == 7) ? 48 : 64;
        unsigned yrow = ybase + (unsigned)(c * 64 * 256);  // f0*64 floats
        unsigned krow = (c & 1) ? kb1 : kb0;
        #pragma unroll 4
        for (int fl = 0; fl < len; ++fl) {
            unsigned long long yv[4];
            asm volatile("ld.shared.v2.u64 {%0,%1}, [%2];"
                         : "=l"(yv[0]), "=l"(yv[1]) : "r"(yrow));
            asm volatile("ld.shared.v2.u64 {%0,%1}, [%2];"
                         : "=l"(yv[2]), "=l"(yv[3]) : "r"(yrow + 16));
            unsigned ka, kbv, kc, kd;
            asm volatile("ld.shared.v4.b32 {%0,%1,%2,%3}, [%4];"
                         : "=r"(ka), "=r"(kbv), "=r"(kc), "=r"(kd) : "r"(krow));
            unsigned long long Kp[4];
            asm("mov.b64 %0, {%1,%1};" : "=l"(Kp[0]) : "r"(ka));
            asm("mov.b64 %0, {%1,%1};" : "=l"(Kp[1]) : "r"(kbv));
            asm("mov.b64 %0, {%1,%1};" : "=l"(Kp[2]) : "r"(kc));
            asm("mov.b64 %0, {%1,%1};" : "=l"(Kp[3]) : "r"(kd));
            #pragma unroll
            for (int mp = 0; mp < 4; ++mp)
                #pragma unroll
                for (int cc = 0; cc < 4; ++cc)
                    asm("fma.rn.f32x2 %0, %1, %2, %0;"
                        : "+l"(acc[mp][cc]) : "l"(yv[mp]), "l"(Kp[cc]));
            yrow += 256;   // 64 floats
            krow += 512;   // 128 floats
        }
        __syncthreads();
        {
            const int cn = c + 2;
            if (cn < 8) {
                const int nv = (cn == 7) ? 1536 : 2048;
                unsigned dst = (cn & 1) ? smaddr(kbuf1) : smaddr(kbuf0);
                const float* src = Kd + (size_t)cn * 8192;
                for (int g = tid; g < nv; g += NTHREADS)
                    cp16(dst + g * 16, src + g * 4);
            }
            asm volatile("cp.async.commit_group;\n" ::: "memory");  // empty group ok
        }
    }

    // ---- epilogue: unpack pairs, add bias, vectorized stores ----
    float4 bv = *(const float4*)(bias + tx * 4);
    const size_t obase = (((size_t)blockIdx.x * 64) + (size_t)ty * 8) * 128 + (size_t)tx * 4;
    #pragma unroll
    for (int mp = 0; mp < 4; ++mp) {
        #pragma unroll
        for (int h = 0; h < 2; ++h) {
            float v0 = __uint_as_float(h ? (unsigned)(acc[mp][0] >> 32) : (unsigned)acc[mp][0]);
            float v1 = __uint_as_float(h ? (unsigned)(acc[mp][1] >> 32) : (unsigned)acc[mp][1]);
            float v2 = __uint_as_float(h ? (unsigned)(acc[mp][2] >> 32) : (unsigned)acc[mp][2]);
            float v3 = __uint_as_float(h ? (unsigned)(acc[mp][3] >> 32) : (unsigned)acc[mp][3]);
            float4 o;
            o.x = v0 + bv.x; o.y = v1 + bv.y; o.z = v2 + bv.z; o.w = v3 + bv.w;
            *(float4*)(out + obase + (size_t)(mp * 2 + h) * 128) = o;
        }
    }
}

extern "C" void kernel_launch(void* const* d_in, const int* in_sizes, int n_in,
                              void* d_out, int out_size) {
    const float* x    = (const float*)d_in[0];
    const float* U0   = (const float*)d_in[1];
    const float* W0   = (const float*)d_in[2];
    const float* Kd   = (const float*)d_in[3];
    const float* bias = (const float*)d_in[4];
    float* o = (float*)d_out;

    const int smem_bytes = 56320 * 4;  // 225,280 B (< 227 KB optin max)
    cudaFuncSetAttribute(tangent_kernel,
                         cudaFuncAttributeMaxDynamicSharedMemorySize, smem_bytes);
    tangent_kernel<<<2048, NTHREADS, smem_bytes>>>(x, U0, W0, Kd, bias, o);
}

// round 8
// speedup vs baseline: 1.3195x; 1.3195x over previous
#include <cuda_runtime.h>
#include <cuda_bf16.h>
#include <cstdint>

// TangentInvariant, 3-kernel pipeline (mma.sync HMMA version; tcgen05 is not
// available because the harness emits PTX with .target sm_103, not sm_103a):
//  1) kprep:  split/transpose dense_kernel -> g_kt [128][1024] bf16 (Kh | Kl)
//  2) phase1: sphere-log + VN + Gram -> g_y [131072][1024] bf16 (yh | yl)
//  3) gemm:   D = yh*Kh + yl*Kh + yh*Kl via mma.sync.m16n8k16 bf16, fp32 acc.

#define NT 256

extern __shared__ char smem_raw[];

// ---------------- scratch (device globals; no runtime alloc) ----------------
__device__ __nv_bfloat16 g_y[131072ull * 1024];   // 256 MB  (yh | yl)
__device__ __nv_bfloat16 g_kt[128 * 1024];        // KT: (Kh | Kl), row n, col k

// ---------------- helpers ----------------
__device__ __forceinline__ unsigned smaddr(const void* p) {
    return (unsigned)__cvta_generic_to_shared(p);
}
__device__ __forceinline__ unsigned sw128(unsigned o) { return o ^ ((o >> 3) & 0x70); }

__device__ __forceinline__ void cp16(unsigned dst, const void* src) {
    asm volatile("cp.async.cg.shared.global [%0], [%1], 16;\n" :: "r"(dst), "l"(src));
}

__device__ __forceinline__ void ldsm_x4(uint32_t& r0, uint32_t& r1,
                                        uint32_t& r2, uint32_t& r3, unsigned a) {
    asm volatile("ldmatrix.sync.aligned.m8n8.x4.shared.b16 {%0,%1,%2,%3}, [%4];"
                 : "=r"(r0), "=r"(r1), "=r"(r2), "=r"(r3) : "r"(a));
}

__device__ __forceinline__ void mma16816(float* c, const uint32_t* a,
                                         uint32_t b0, uint32_t b1) {
    asm volatile(
        "mma.sync.aligned.m16n8k16.row.col.f32.bf16.bf16.f32 "
        "{%0,%1,%2,%3}, {%4,%5,%6,%7}, {%8,%9}, {%0,%1,%2,%3};"
        : "+f"(c[0]), "+f"(c[1]), "+f"(c[2]), "+f"(c[3])
        : "r"(a[0]), "r"(a[1]), "r"(a[2]), "r"(a[3]), "r"(b0), "r"(b1));
}

// ---------------- kernel 1: transpose + split dense_kernel ----------------
__global__ void kprep_kernel(const float* __restrict__ Kd) {
    int idx = blockIdx.x * blockDim.x + threadIdx.x;   // idx = n*1024 + k
    if (idx >= 128 * 1024) return;
    int n = idx >> 10, k = idx & 1023;
    int kk = k & 511;
    float v = (kk < 496) ? Kd[kk * 128 + n] : 0.0f;
    __nv_bfloat16 hi = __float2bfloat16(v);
    if (k < 512) {
        g_kt[idx] = hi;
    } else {
        g_kt[idx] = __float2bfloat16(v - __bfloat162float(hi));
    }
}

// ---------------- kernel 2: phase-1 producer (64 tokens/block) ----------------
__global__ __launch_bounds__(NT)
void phase1_kernel(const float* __restrict__ x,
                   const float* __restrict__ U0,
                   const float* __restrict__ W0)
{
    float* sm = (float*)smem_raw;
    float* xs  = sm;           // 64*96  = 6144
    float* vsm = sm + 6144;    // 64*93  = 5952
    float* wsm = sm + 12096;   // 64*48  = 3072
    float* Usm = sm + 15168;   // 496
    float* Wsm = sm + 15664;   // 496  -> total 16160 floats

    const int tid = threadIdx.x;

    {
        const float4* src = (const float4*)(x + (size_t)blockIdx.x * (64 * 96));
        float4* dst = (float4*)xs;
        for (int g = tid; g < 1536; g += NT) dst[g] = src[g];
        for (int g = tid; g < 496; g += NT) { Usm[g] = U0[g]; Wsm[g] = W0[g]; }
    }
    __syncthreads();

    // sphere log -> v
    for (int idx = tid; idx < 64 * 31; idx += NT) {
        int t = idx / 31;
        int j = idx - t * 31;
        const float* xt = xs + t * 96;
        float px = xt[0], py = xt[1], pz = xt[2];
        const float* q = xt + 3 + j * 3;
        float qx = q[0], qy = q[1], qz = q[2];
        float cs = px * qx + py * qy + pz * qz;
        cs = fminf(1.0f, fmaxf(-1.0f, cs));
        float th = acosf(cs);
        float fac = (th < 1e-6f) ? 1.0f : th / sinf(th);
        float* vo = vsm + t * 93 + j * 3;
        vo[0] = fac * (qx - cs * px);
        vo[1] = fac * (qy - cs * py);
        vo[2] = fac * (qz - cs * pz);
    }
    __syncthreads();

    // VN layer -> w
    for (int idx = tid; idx < 64 * 16; idx += NT) {
        int t = idx >> 4;
        int i = idx & 15;
        const float* vb = vsm + t * 93;
        const float* Ur = Usm + i * 31;
        const float* Wr = Wsm + i * 31;
        float kx = 0.f, ky = 0.f, kz = 0.f, qx = 0.f, qy = 0.f, qz = 0.f;
        #pragma unroll
        for (int j = 0; j < 31; ++j) {
            float u = Ur[j], w_ = Wr[j];
            float vx = vb[j * 3 + 0], vy = vb[j * 3 + 1], vz = vb[j * 3 + 2];
            kx += u * vx;  ky += u * vy;  kz += u * vz;
            qx += w_ * vx; qy += w_ * vy; qz += w_ * vz;
        }
        float sq = kx * kx + ky * ky + kz * kz + 2.2204460492503131e-16f;
        float dt = qx * kx + qy * ky + qz * kz;
        float r = 0.8f * fmaxf(-dt, 0.0f) / sq;
        float* wo = wsm + t * 48 + i * 3;
        wo[0] = qx + r * kx;
        wo[1] = qy + r * ky;
        wo[2] = qz + r * kz;
    }
    __syncthreads();

    // Gram features -> split bf16 to global: yh at col f, yl at col 512+f
    const size_t mbase = (size_t)blockIdx.x * 64;
    for (int idx = tid; idx < 64 * 512; idx += NT) {
        int t = idx >> 9;
        int f = idx & 511;
        float y = 0.0f;
        if (f < 496) {
            int i = f >> 4;
            int kk = f & 15;
            const float* vv = vsm + t * 93 + i * 3;
            const float* ww = wsm + t * 48 + kk * 3;
            y = vv[0] * ww[0] + vv[1] * ww[1] + vv[2] * ww[2];
        }
        __nv_bfloat16 hi = __float2bfloat16(y);
        __nv_bfloat16 lo = __float2bfloat16(y - __bfloat162float(hi));
        size_t o = (mbase + t) * 1024 + f;
        g_y[o]       = hi;
        g_y[o + 512] = lo;
    }
}

// ---------------- kernel 3: HMMA GEMM ----------------
// Block: 128 tokens x 128 out-ch. 24 K-chunks of 64:
//   c in [0,8):   A = yh[c*64..]       B = Kh[c*64..]
//   c in [8,16):  A = yl[(c-8)*64..]   B = Kh[(c-8)*64..]
//   c in [16,24): A = yh[(c-16)*64..]  B = Kl[(c-16)*64..]
// 3-stage cp.async pipeline; stage = 16KB A + 16KB B (sw128 swizzled 128B rows).
static constexpr int STAGE_BYTES = 32768;
static constexpr int SMEM_GEMM   = 3 * STAGE_BYTES;   // 96 KB

__device__ __forceinline__ int gemm_a_col(int c) {
    return (c < 8) ? c * 64 : (c < 16 ? 512 + (c - 8) * 64 : (c - 16) * 64);
}
__device__ __forceinline__ int gemm_b_col(int c) {
    return (c < 8) ? c * 64 : (c < 16 ? (c - 8) * 64 : 512 + (c - 16) * 64);
}

__device__ __forceinline__ void gemm_load_chunk(unsigned smem_u32, int tid,
                                                int stage, size_t m0, int c) {
    const unsigned abase = smem_u32 + stage * STAGE_BYTES;
    const unsigned bbase = abase + 16384;
    const int ac = gemm_a_col(c);
    const int bc = gemm_b_col(c);
    #pragma unroll
    for (int it = 0; it < 4; ++it) {
        int g = tid + it * NT;          // 0..1023
        int row = g >> 3, seg = g & 7;  // 128 rows x 8 x 16B
        unsigned off = sw128((unsigned)(row * 128 + seg * 16));
        cp16(abase + off, g_y + (m0 + (size_t)row) * 1024 + ac + seg * 8);
        cp16(bbase + off, g_kt + (size_t)row * 1024 + bc + seg * 8);
    }
    asm volatile("cp.async.commit_group;\n" ::: "memory");
}

__global__ __launch_bounds__(NT, 2)
void gemm_kernel(const float* __restrict__ bias, float* __restrict__ out)
{
    const unsigned smem_u32 = smaddr(smem_raw);
    const int tid = threadIdx.x;
    const int wid = tid >> 5;
    const int lid = tid & 31;
    const size_t m0 = (size_t)blockIdx.x * 128;

    // warp grid 2 (M) x 4 (N): warp tile 64x32
    const int m_base = (wid & 1) * 64;
    const int n_base = (wid >> 1) * 32;

    // ldmatrix per-lane geometry
    const unsigned a_row = (unsigned)(m_base + ((lid >> 3) & 1) * 8 + (lid & 7));
    const unsigned a_cb  = (unsigned)(((lid >> 4) & 1) * 16);
    const unsigned b_row = (unsigned)(n_base + ((lid >> 4) & 1) * 8 + (lid & 7));
    const unsigned b_cb  = (unsigned)(((lid >> 3) & 1) * 16);

    float acc[4][4][4];   // [mt][nt][frag]
    #pragma unroll
    for (int i = 0; i < 4; ++i)
        #pragma unroll
        for (int j = 0; j < 4; ++j)
            #pragma unroll
            for (int k = 0; k < 4; ++k) acc[i][j][k] = 0.0f;

    // prologue: stages 0,1,2 <- chunks 0,1,2
    gemm_load_chunk(smem_u32, tid, 0, m0, 0);
    gemm_load_chunk(smem_u32, tid, 1, m0, 1);
    gemm_load_chunk(smem_u32, tid, 2, m0, 2);

    int stage = 0;
    for (int c = 0; c < 24; ++c) {
        asm volatile("cp.async.wait_group 2;\n" ::: "memory");
        __syncthreads();

        const unsigned abase = smem_u32 + stage * STAGE_BYTES;
        const unsigned bbase = abase + 16384;

        #pragma unroll
        for (int ks = 0; ks < 4; ++ks) {
            uint32_t a[4][4];
            #pragma unroll
            for (int mt = 0; mt < 4; ++mt) {
                unsigned off = (a_row + mt * 16) * 128 + a_cb + ks * 32;
                ldsm_x4(a[mt][0], a[mt][1], a[mt][2], a[mt][3], abase + sw128(off));
            }
            uint32_t b[4][2];
            #pragma unroll
            for (int ntp = 0; ntp < 2; ++ntp) {
                unsigned off = (b_row + ntp * 16) * 128 + b_cb + ks * 32;
                uint32_t r0, r1, r2, r3;
                ldsm_x4(r0, r1, r2, r3, bbase + sw128(off));
                b[ntp * 2 + 0][0] = r0; b[ntp * 2 + 0][1] = r1;
                b[ntp * 2 + 1][0] = r2; b[ntp * 2 + 1][1] = r3;
            }
            #pragma unroll
            for (int mt = 0; mt < 4; ++mt)
                #pragma unroll
                for (int nt = 0; nt < 4; ++nt)
                    mma16816(acc[mt][nt], a[mt], b[nt][0], b[nt][1]);
        }

        __syncthreads();
        if (c + 3 < 24) gemm_load_chunk(smem_u32, tid, stage, m0, c + 3);
        else asm volatile("cp.async.commit_group;\n" ::: "memory"); // keep counts aligned
        stage = (stage + 1) % 3;
    }

    // epilogue: acc -> out (+bias)
    const int gr = lid >> 2;            // group row 0..7
    const int gc = (lid & 3) * 2;       // col pair base
    #pragma unroll
    for (int nt = 0; nt < 4; ++nt) {
        const int n_ = n_base + nt * 8 + gc;
        const float b0 = bias[n_], b1 = bias[n_ + 1];
        #pragma unroll
        for (int mt = 0; mt < 4; ++mt) {
            const size_t m = m0 + (size_t)(m_base + mt * 16 + gr);
            float2 o0; o0.x = acc[mt][nt][0] + b0; o0.y = acc[mt][nt][1] + b1;
            float2 o1; o1.x = acc[mt][nt][2] + b0; o1.y = acc[mt][nt][3] + b1;
            *(float2*)(out + m * 128 + n_)        = o0;
            *(float2*)(out + (m + 8) * 128 + n_)  = o1;
        }
    }
}

// ---------------- launch ----------------
extern "C" void kernel_launch(void* const* d_in, const int* in_sizes, int n_in,
                              void* d_out, int out_size) {
    const float* x    = (const float*)d_in[0];
    const float* U0   = (const float*)d_in[1];
    const float* W0   = (const float*)d_in[2];
    const float* Kd   = (const float*)d_in[3];
    const float* bias = (const float*)d_in[4];
    float* o = (float*)d_out;

    cudaFuncSetAttribute(phase1_kernel,
                         cudaFuncAttributeMaxDynamicSharedMemorySize, 16160 * 4);
    cudaFuncSetAttribute(gemm_kernel,
                         cudaFuncAttributeMaxDynamicSharedMemorySize, SMEM_GEMM);

    kprep_kernel<<<512, NT>>>(Kd);
    phase1_kernel<<<2048, NT, 16160 * 4>>>(x, U0, W0);
    gemm_kernel<<<1024, NT, SMEM_GEMM>>>(bias, o);
}

// round 9
// speedup vs baseline: 1.3481x; 1.0217x over previous
#include <cuda_runtime.h>
#include <cuda_bf16.h>
#include <cstdint>

// TangentInvariant — fused single-pass version.
//  kernel 1 (kprep): split/transpose dense_kernel -> g_kt [128][1024] bf16 (Kh|Kl)
//  kernel 2 (fused): per 64-token block:
//     phase 1: sphere-log + VN + Gram -> split bf16 y tile in SMEM [64][1024]
//     phase 2: HMMA GEMM  out[64,128] = yh*Kh + yl*Kh + yh*Kl  (fp32 acc)
//  y never touches global memory (saves ~640 MB of HBM round-trip vs R8).

#define NT 256

extern __shared__ char smem_raw[];

// dense_kernel transposed+split: row n in [0,128), col k in [0,1024): (Kh | Kl)
__device__ __nv_bfloat16 g_kt[128 * 1024];

// ---------------- helpers ----------------
__device__ __forceinline__ unsigned smaddr(const void* p) {
    return (unsigned)__cvta_generic_to_shared(p);
}
__device__ __forceinline__ unsigned sw128(unsigned o) { return o ^ ((o >> 3) & 0x70); }

__device__ __forceinline__ void cp16(unsigned dst, const void* src) {
    asm volatile("cp.async.cg.shared.global [%0], [%1], 16;\n" :: "r"(dst), "l"(src));
}

__device__ __forceinline__ void ldsm_x4(uint32_t& r0, uint32_t& r1,
                                        uint32_t& r2, uint32_t& r3, unsigned a) {
    asm volatile("ldmatrix.sync.aligned.m8n8.x4.shared.b16 {%0,%1,%2,%3}, [%4];"
                 : "=r"(r0), "=r"(r1), "=r"(r2), "=r"(r3) : "r"(a));
}

__device__ __forceinline__ void mma16816(float* c, const uint32_t* a,
                                         uint32_t b0, uint32_t b1) {
    asm volatile(
        "mma.sync.aligned.m16n8k16.row.col.f32.bf16.bf16.f32 "
        "{%0,%1,%2,%3}, {%4,%5,%6,%7}, {%8,%9}, {%0,%1,%2,%3};"
        : "+f"(c[0]), "+f"(c[1]), "+f"(c[2]), "+f"(c[3])
        : "r"(a[0]), "r"(a[1]), "r"(a[2]), "r"(a[3]), "r"(b0), "r"(b1));
}

// ---------------- kernel 1: transpose + split dense_kernel ----------------
__global__ void kprep_kernel(const float* __restrict__ Kd) {
    int idx = blockIdx.x * blockDim.x + threadIdx.x;   // idx = n*1024 + k
    if (idx >= 128 * 1024) return;
    int n = idx >> 10, k = idx & 1023;
    int kk = k & 511;
    float v = (kk < 496) ? Kd[kk * 128 + n] : 0.0f;
    __nv_bfloat16 hi = __float2bfloat16(v);
    if (k < 512) g_kt[idx] = hi;
    else         g_kt[idx] = __float2bfloat16(v - __bfloat162float(hi));
}

// ---------------- fused kernel ----------------
// SMEM layout (bytes):
//   [0, 131072)          ysm  : y split bf16, token-major rows of 2048 B,
//                               element (t,f) at t*2048 + (((f>>3)^(t&7))<<4) + (f&7)*2
//   [131072, 163840)     Bbuf : 2 x 16 KB B chunk buffers (128 rows x 128 B, sw128)
//   [163840, 228480)     phase-1 scratch: 16160 floats
static constexpr int YSM_OFF   = 0;
static constexpr int BBUF_OFF  = 131072;
static constexpr int P1_OFF    = 163840;
static constexpr int SMEM_FUSE = 228480;

// pass structure: 24 K-chunks of 64
//   c in [0,8):   A = yh cols c*64        B = Kh cols c*64
//   c in [8,16):  A = yl cols 512+(c-8)*64  B = Kh cols (c-8)*64
//   c in [16,24): A = yh cols (c-16)*64     B = Kl cols 512+(c-16)*64
__device__ __forceinline__ int a_colbase(int c) {
    return (c < 8) ? c * 64 : (c < 16 ? 512 + (c - 8) * 64 : (c - 16) * 64);
}
__device__ __forceinline__ int b_colbase(int c) {
    return (c < 16) ? (c & 7) * 64 : 512 + (c - 16) * 64;
}

__device__ __forceinline__ void load_b_chunk(unsigned bbase, int tid, int stage, int c) {
    const unsigned dst = bbase + stage * 16384;
    const int bc = b_colbase(c);
    #pragma unroll
    for (int it = 0; it < 4; ++it) {
        int g = tid + it * NT;          // 0..1023
        int row = g >> 3, seg = g & 7;  // 128 rows x 8 x 16B
        unsigned off = sw128((unsigned)(row * 128 + seg * 16));
        cp16(dst + off, g_kt + (size_t)row * 1024 + bc + seg * 8);
    }
    asm volatile("cp.async.commit_group;\n" ::: "memory");
}

__global__ __launch_bounds__(NT, 1)
void fused_kernel(const float* __restrict__ x,
                  const float* __restrict__ U0,
                  const float* __restrict__ W0,
                  const float* __restrict__ bias,
                  float* __restrict__ out)
{
    const unsigned smem_u32 = smaddr(smem_raw);
    const unsigned ybase = smem_u32 + YSM_OFF;
    const unsigned bbase = smem_u32 + BBUF_OFF;
    const int tid = threadIdx.x;

    // ---- kick off B prefetch for chunks 0,1 immediately (L2-resident) ----
    load_b_chunk(bbase, tid, 0, 0);
    load_b_chunk(bbase, tid, 1, 1);

    // ================= phase 1 =================
    {
        float* sm  = (float*)(smem_raw + P1_OFF);
        float* xs  = sm;           // 64*96
        float* vsm = sm + 6144;    // 64*93
        float* wsm = sm + 12096;   // 64*48
        float* Usm = sm + 15168;   // 496
        float* Wsm = sm + 15664;   // 496

        {
            const float4* src = (const float4*)(x + (size_t)blockIdx.x * (64 * 96));
            float4* dst = (float4*)xs;
            for (int g = tid; g < 1536; g += NT) dst[g] = src[g];
            for (int g = tid; g < 496; g += NT) { Usm[g] = U0[g]; Wsm[g] = W0[g]; }
        }
        __syncthreads();

        // sphere log -> v
        for (int idx = tid; idx < 64 * 31; idx += NT) {
            int t = idx / 31;
            int j = idx - t * 31;
            const float* xt = xs + t * 96;
            float px = xt[0], py = xt[1], pz = xt[2];
            const float* q = xt + 3 + j * 3;
            float qx = q[0], qy = q[1], qz = q[2];
            float cs = px * qx + py * qy + pz * qz;
            cs = fminf(1.0f, fmaxf(-1.0f, cs));
            float th = acosf(cs);
            float fac = (th < 1e-6f) ? 1.0f : th / sinf(th);
            float* vo = vsm + t * 93 + j * 3;
            vo[0] = fac * (qx - cs * px);
            vo[1] = fac * (qy - cs * py);
            vo[2] = fac * (qz - cs * pz);
        }
        __syncthreads();

        // VN layer -> w
        for (int idx = tid; idx < 64 * 16; idx += NT) {
            int t = idx >> 4;
            int i = idx & 15;
            const float* vb = vsm + t * 93;
            const float* Ur = Usm + i * 31;
            const float* Wr = Wsm + i * 31;
            float kx = 0.f, ky = 0.f, kz = 0.f, qx = 0.f, qy = 0.f, qz = 0.f;
            #pragma unroll
            for (int j = 0; j < 31; ++j) {
                float u = Ur[j], w_ = Wr[j];
                float vx = vb[j * 3 + 0], vy = vb[j * 3 + 1], vz = vb[j * 3 + 2];
                kx += u * vx;  ky += u * vy;  kz += u * vz;
                qx += w_ * vx; qy += w_ * vy; qz += w_ * vz;
            }
            float sq = kx * kx + ky * ky + kz * kz + 2.2204460492503131e-16f;
            float dt = qx * kx + qy * ky + qz * kz;
            float r = 0.8f * fmaxf(-dt, 0.0f) / sq;
            float* wo = wsm + t * 48 + i * 3;
            wo[0] = qx + r * kx;
            wo[1] = qy + r * ky;
            wo[2] = qz + r * kz;
        }
        __syncthreads();

        // Gram -> split bf16 into ysm (2 features per iter, paired 4B stores)
        for (int idx = tid; idx < 64 * 256; idx += NT) {
            int t = idx >> 8;
            int fp = (idx & 255) * 2;
            float y0 = 0.0f, y1 = 0.0f;
            if (fp < 496) {
                const float* vv = vsm + t * 93 + (fp >> 4) * 3;
                const float* w0 = wsm + t * 48 + (fp & 15) * 3;
                y0 = vv[0] * w0[0] + vv[1] * w0[1] + vv[2] * w0[2];
                int f1 = fp + 1;
                const float* vv1 = vsm + t * 93 + (f1 >> 4) * 3;
                const float* w1 = wsm + t * 48 + (f1 & 15) * 3;
                y1 = vv1[0] * w1[0] + vv1[1] * w1[1] + vv1[2] * w1[2];
            }
            __nv_bfloat16 h0 = __float2bfloat16(y0);
            __nv_bfloat16 h1 = __float2bfloat16(y1);
            __nv_bfloat16 l0 = __float2bfloat16(y0 - __bfloat162float(h0));
            __nv_bfloat16 l1 = __float2bfloat16(y1 - __bfloat162float(h1));
            const int x7 = t & 7;
            // hi pair at (t, fp)
            unsigned ga = (unsigned)((fp >> 3) ^ x7);
            unsigned ah = ybase + (unsigned)t * 2048 + (ga << 4) + (unsigned)(fp & 7) * 2;
            // lo pair at (t, 512+fp)
            unsigned gb = (unsigned)(((512 + fp) >> 3) ^ x7);
            unsigned al = ybase + (unsigned)t * 2048 + (gb << 4) + (unsigned)(fp & 7) * 2;
            unsigned hv = ((unsigned)*(uint16_t*)&h1 << 16) | *(uint16_t*)&h0;
            unsigned lv = ((unsigned)*(uint16_t*)&l1 << 16) | *(uint16_t*)&l0;
            asm volatile("st.shared.b32 [%0], %1;" :: "r"(ah), "r"(hv) : "memory");
            asm volatile("st.shared.b32 [%0], %1;" :: "r"(al), "r"(lv) : "memory");
        }
    }
    __syncthreads();

    // ================= phase 2: GEMM 64x128x1536 =================
    const int wid = tid >> 5;
    const int lid = tid & 31;
    // warp grid: 2 (M) x 4 (N); warp tile 32x32
    const int m_base = (wid & 1) * 32;
    const int n_base = (wid >> 1) * 32;

    const int a_r  = m_base + ((lid >> 3) & 1) * 8 + (lid & 7);
    const int a_c8 = (lid >> 4) & 1;            // +8 elems
    const int ax7  = a_r & 7;
    const unsigned a_rowaddr = ybase + (unsigned)a_r * 2048;

    const int b_r  = ((lid >> 4) & 1) * 8 + (lid & 7);  // within 16-row n-tile
    const unsigned b_cb = (unsigned)(((lid >> 3) & 1) * 16);

    float acc[2][4][4];
    #pragma unroll
    for (int i = 0; i < 2; ++i)
        #pragma unroll
        for (int j = 0; j < 4; ++j)
            #pragma unroll
            for (int k = 0; k < 4; ++k) acc[i][j][k] = 0.0f;

    int stage = 0;
    for (int c = 0; c < 24; ++c) {
        asm volatile("cp.async.wait_group 1;\n" ::: "memory");
        __syncthreads();

        const unsigned bchunk = bbase + stage * 16384;
        const int acol = a_colbase(c);

        #pragma unroll
        for (int ks = 0; ks < 4; ++ks) {
            // A fragments: 2 m-tiles of 16 rows
            uint32_t a[2][4];
            {
                int agrp = (acol >> 3) + ks * 2 + a_c8;
                unsigned g = (unsigned)(agrp ^ ax7);
                unsigned ad0 = a_rowaddr + (g << 4);
                ldsm_x4(a[0][0], a[0][1], a[0][2], a[0][3], ad0);
                ldsm_x4(a[1][0], a[1][1], a[1][2], a[1][3], ad0 + 16 * 2048);
            }
            // B fragments: 4 n-tiles of 8 (2 ldsm.x4 over 2 16-row tiles)
            uint32_t b[4][2];
            #pragma unroll
            for (int ntp = 0; ntp < 2; ++ntp) {
                unsigned off = (unsigned)((n_base + ntp * 16 + b_r) * 128)
                             + (unsigned)(ks * 32) + b_cb;
                uint32_t r0, r1, r2, r3;
                ldsm_x4(r0, r1, r2, r3, bchunk + sw128(off));
                b[ntp * 2 + 0][0] = r0; b[ntp * 2 + 0][1] = r1;
                b[ntp * 2 + 1][0] = r2; b[ntp * 2 + 1][1] = r3;
            }
            #pragma unroll
            for (int mt = 0; mt < 2; ++mt)
                #pragma unroll
                for (int nt = 0; nt < 4; ++nt)
                    mma16816(acc[mt][nt], a[mt], b[nt][0], b[nt][1]);
        }

        __syncthreads();
        if (c + 2 < 24) load_b_chunk(bbase, tid, stage, c + 2);
        else asm volatile("cp.async.commit_group;\n" ::: "memory");
        stage ^= 1;
    }

    // ---- epilogue ----
    const size_t m0 = (size_t)blockIdx.x * 64;
    const int gr = lid >> 2;
    const int gc = (lid & 3) * 2;
    #pragma unroll
    for (int nt = 0; nt < 4; ++nt) {
        const int n_ = n_base + nt * 8 + gc;
        const float b0 = bias[n_], b1 = bias[n_ + 1];
        #pragma unroll
        for (int mt = 0; mt < 2; ++mt) {
            const size_t m = m0 + (size_t)(m_base + mt * 16 + gr);
            float2 o0; o0.x = acc[mt][nt][0] + b0; o0.y = acc[mt][nt][1] + b1;
            float2 o1; o1.x = acc[mt][nt][2] + b0; o1.y = acc[mt][nt][3] + b1;
            *(float2*)(out + m * 128 + n_)       = o0;
            *(float2*)(out + (m + 8) * 128 + n_) = o1;
        }
    }
}

// ---------------- launch ----------------
extern "C" void kernel_launch(void* const* d_in, const int* in_sizes, int n_in,
                              void* d_out, int out_size) {
    const float* x    = (const float*)d_in[0];
    const float* U0   = (const float*)d_in[1];
    const float* W0   = (const float*)d_in[2];
    const float* Kd   = (const float*)d_in[3];
    const float* bias = (const float*)d_in[4];
    float* o = (float*)d_out;

    cudaFuncSetAttribute(fused_kernel,
                         cudaFuncAttributeMaxDynamicSharedMemorySize, SMEM_FUSE);

    kprep_kernel<<<512, NT>>>(Kd);
    fused_kernel<<<2048, NT, SMEM_FUSE>>>(x, U0, W0, bias, o);
}

// round 10
// speedup vs baseline: 1.4573x; 1.0810x over previous
#include <cuda_runtime.h>
#include <cuda_bf16.h>
#include <cstdint>

// TangentInvariant — fused single-pass, 512 threads, 4-stage B pipeline.
//  kernel 1 (kprep): split/transpose dense_kernel -> g_kt [128][1024] bf16 (Kh|Kl)
//  kernel 2 (fused): per 64-token block:
//     phase 1: sphere-log + VN + Gram -> split bf16 y tile in SMEM [64][1024]
//     phase 2: HMMA GEMM  out[64,128] = yh*Kh + yl*Kh + yh*Kl  (fp32 acc)

#define NT 512

extern __shared__ char smem_raw[];

// dense_kernel transposed+split: row n in [0,128), col k in [0,1024): (Kh | Kl)
__device__ __nv_bfloat16 g_kt[128 * 1024];

// ---------------- helpers ----------------
__device__ __forceinline__ unsigned smaddr(const void* p) {
    return (unsigned)__cvta_generic_to_shared(p);
}
__device__ __forceinline__ unsigned sw128(unsigned o) { return o ^ ((o >> 3) & 0x70); }

__device__ __forceinline__ void cp16(unsigned dst, const void* src) {
    asm volatile("cp.async.cg.shared.global [%0], [%1], 16;\n" :: "r"(dst), "l"(src));
}

__device__ __forceinline__ void ldsm_x4(uint32_t& r0, uint32_t& r1,
                                        uint32_t& r2, uint32_t& r3, unsigned a) {
    asm volatile("ldmatrix.sync.aligned.m8n8.x4.shared.b16 {%0,%1,%2,%3}, [%4];"
                 : "=r"(r0), "=r"(r1), "=r"(r2), "=r"(r3) : "r"(a));
}

__device__ __forceinline__ void mma16816(float* c, const uint32_t* a,
                                         uint32_t b0, uint32_t b1) {
    asm volatile(
        "mma.sync.aligned.m16n8k16.row.col.f32.bf16.bf16.f32 "
        "{%0,%1,%2,%3}, {%4,%5,%6,%7}, {%8,%9}, {%0,%1,%2,%3};"
        : "+f"(c[0]), "+f"(c[1]), "+f"(c[2]), "+f"(c[3])
        : "r"(a[0]), "r"(a[1]), "r"(a[2]), "r"(a[3]), "r"(b0), "r"(b1));
}

// ---------------- kernel 1: transpose + split dense_kernel ----------------
__global__ void kprep_kernel(const float* __restrict__ Kd) {
    int idx = blockIdx.x * blockDim.x + threadIdx.x;   // idx = n*1024 + k
    if (idx >= 128 * 1024) return;
    int n = idx >> 10, k = idx & 1023;
    int kk = k & 511;
    float v = (kk < 496) ? Kd[kk * 128 + n] : 0.0f;
    __nv_bfloat16 hi = __float2bfloat16(v);
    if (k < 512) g_kt[idx] = hi;
    else         g_kt[idx] = __float2bfloat16(v - __bfloat162float(hi));
}

// ---------------- fused kernel ----------------
// SMEM layout (bytes):
//   [0, 131072)          ysm  : y split bf16, token-major rows of 2048 B,
//                               element (t,f) at t*2048 + (((f>>3)^(t&7))<<4) + (f&7)*2
//   [131072, 163840)     B stages 0,1 (16 KB each, 128 rows x 128 B, sw128)
//   [163840, 228480)     phase-1 scratch (16160 floats); after phase 1 the
//                        first 32 KB are reused as B stages 2,3.
static constexpr int YSM_OFF   = 0;
static constexpr int BBUF_OFF  = 131072;
static constexpr int P1_OFF    = 163840;
static constexpr int SMEM_FUSE = 228480;

// pass structure: 24 K-chunks of 64
//   c in [0,8):   A = yh cols c*64          B = Kh cols c*64
//   c in [8,16):  A = yl cols 512+(c-8)*64  B = Kh cols (c-8)*64
//   c in [16,24): A = yh cols (c-16)*64     B = Kl cols 512+(c-16)*64
__device__ __forceinline__ int a_colbase(int c) {
    return (c < 8) ? c * 64 : (c < 16 ? 512 + (c - 8) * 64 : (c - 16) * 64);
}
__device__ __forceinline__ int b_colbase(int c) {
    return (c < 16) ? (c & 7) * 64 : 512 + (c - 16) * 64;
}
__device__ __forceinline__ unsigned stage_addr(unsigned smem_u32, int s) {
    return (s < 2) ? smem_u32 + BBUF_OFF + s * 16384
                   : smem_u32 + P1_OFF + (s - 2) * 16384;
}

__device__ __forceinline__ void load_b_chunk(unsigned smem_u32, int tid, int stage, int c) {
    const unsigned dst = stage_addr(smem_u32, stage);
    const int bc = b_colbase(c);
    #pragma unroll
    for (int it = 0; it < 2; ++it) {
        int g = tid + it * NT;          // 0..1023
        int row = g >> 3, seg = g & 7;  // 128 rows x 8 x 16B
        unsigned off = sw128((unsigned)(row * 128 + seg * 16));
        cp16(dst + off, g_kt + (size_t)row * 1024 + bc + seg * 8);
    }
    asm volatile("cp.async.commit_group;\n" ::: "memory");
}

__global__ __launch_bounds__(NT, 1)
void fused_kernel(const float* __restrict__ x,
                  const float* __restrict__ U0,
                  const float* __restrict__ W0,
                  const float* __restrict__ bias,
                  float* __restrict__ out)
{
    const unsigned smem_u32 = smaddr(smem_raw);
    const unsigned ybase = smem_u32 + YSM_OFF;
    const int tid = threadIdx.x;

    // ---- kick off B prefetch for chunks 0,1 (stages 0,1 — disjoint from p1 scratch) ----
    load_b_chunk(smem_u32, tid, 0, 0);
    load_b_chunk(smem_u32, tid, 1, 1);

    // ================= phase 1 =================
    {
        float* sm  = (float*)(smem_raw + P1_OFF);
        float* xs  = sm;           // 64*96
        float* vsm = sm + 6144;    // 64*93
        float* wsm = sm + 12096;   // 64*48
        float* Usm = sm + 15168;   // 496
        float* Wsm = sm + 15664;   // 496

        {
            const float4* src = (const float4*)(x + (size_t)blockIdx.x * (64 * 96));
            float4* dst = (float4*)xs;
            for (int g = tid; g < 1536; g += NT) dst[g] = src[g];
            for (int g = tid; g < 496; g += NT) { Usm[g] = U0[g]; Wsm[g] = W0[g]; }
        }
        __syncthreads();

        // sphere log -> v
        for (int idx = tid; idx < 64 * 31; idx += NT) {
            int t = idx / 31;
            int j = idx - t * 31;
            const float* xt = xs + t * 96;
            float px = xt[0], py = xt[1], pz = xt[2];
            const float* q = xt + 3 + j * 3;
            float qx = q[0], qy = q[1], qz = q[2];
            float cs = px * qx + py * qy + pz * qz;
            cs = fminf(1.0f, fmaxf(-1.0f, cs));
            float th = acosf(cs);
            float fac = (th < 1e-6f) ? 1.0f : th / sinf(th);
            float* vo = vsm + t * 93 + j * 3;
            vo[0] = fac * (qx - cs * px);
            vo[1] = fac * (qy - cs * py);
            vo[2] = fac * (qz - cs * pz);
        }
        __syncthreads();

        // VN layer -> w
        for (int idx = tid; idx < 64 * 16; idx += NT) {
            int t = idx >> 4;
            int i = idx & 15;
            const float* vb = vsm + t * 93;
            const float* Ur = Usm + i * 31;
            const float* Wr = Wsm + i * 31;
            float kx = 0.f, ky = 0.f, kz = 0.f, qx = 0.f, qy = 0.f, qz = 0.f;
            #pragma unroll
            for (int j = 0; j < 31; ++j) {
                float u = Ur[j], w_ = Wr[j];
                float vx = vb[j * 3 + 0], vy = vb[j * 3 + 1], vz = vb[j * 3 + 2];
                kx += u * vx;  ky += u * vy;  kz += u * vz;
                qx += w_ * vx; qy += w_ * vy; qz += w_ * vz;
            }
            float sq = kx * kx + ky * ky + kz * kz + 2.2204460492503131e-16f;
            float dt = qx * kx + qy * ky + qz * kz;
            float r = 0.8f * fmaxf(-dt, 0.0f) / sq;
            float* wo = wsm + t * 48 + i * 3;
            wo[0] = qx + r * kx;
            wo[1] = qy + r * ky;
            wo[2] = qz + r * kz;
        }
        __syncthreads();

        // Gram -> split bf16 into ysm (2 features per iter, paired 4B stores)
        for (int idx = tid; idx < 64 * 256; idx += NT) {
            int t = idx >> 8;
            int fp = (idx & 255) * 2;
            float y0 = 0.0f, y1 = 0.0f;
            if (fp < 496) {
                const float* vv = vsm + t * 93 + (fp >> 4) * 3;
                const float* w0 = wsm + t * 48 + (fp & 15) * 3;
                y0 = vv[0] * w0[0] + vv[1] * w0[1] + vv[2] * w0[2];
                int f1 = fp + 1;
                const float* vv1 = vsm + t * 93 + (f1 >> 4) * 3;
                const float* w1 = wsm + t * 48 + (f1 & 15) * 3;
                y1 = vv1[0] * w1[0] + vv1[1] * w1[1] + vv1[2] * w1[2];
            }
            __nv_bfloat16 h0 = __float2bfloat16(y0);
            __nv_bfloat16 h1 = __float2bfloat16(y1);
            __nv_bfloat16 l0 = __float2bfloat16(y0 - __bfloat162float(h0));
            __nv_bfloat16 l1 = __float2bfloat16(y1 - __bfloat162float(h1));
            const int x7 = t & 7;
            unsigned ga = (unsigned)((fp >> 3) ^ x7);
            unsigned ah = ybase + (unsigned)t * 2048 + (ga << 4) + (unsigned)(fp & 7) * 2;
            unsigned gb = (unsigned)(((512 + fp) >> 3) ^ x7);
            unsigned al = ybase + (unsigned)t * 2048 + (gb << 4) + (unsigned)(fp & 7) * 2;
            unsigned hv = ((unsigned)*(uint16_t*)&h1 << 16) | *(uint16_t*)&h0;
            unsigned lv = ((unsigned)*(uint16_t*)&l1 << 16) | *(uint16_t*)&l0;
            asm volatile("st.shared.b32 [%0], %1;" :: "r"(ah), "r"(hv) : "memory");
            asm volatile("st.shared.b32 [%0], %1;" :: "r"(al), "r"(lv) : "memory");
        }
    }
    __syncthreads();   // phase-1 scratch now dead; stages 2,3 may overwrite it

    // prefetch chunk 2 into stage 2 (overlays dead scratch)
    load_b_chunk(smem_u32, tid, 2, 2);

    // ================= phase 2: GEMM 64x128x1536 =================
    const int wid = tid >> 5;
    const int lid = tid & 31;
    // warp grid: 4 (M) x 4 (N); warp tile 16x32
    const int m_base = (wid & 3) * 16;
    const int n_base = (wid >> 2) * 32;

    const int a_r  = m_base + ((lid >> 3) & 1) * 8 + (lid & 7);
    const int a_c8 = (lid >> 4) & 1;            // +8 elems in k
    const int ax7  = a_r & 7;
    const unsigned a_rowaddr = ybase + (unsigned)a_r * 2048;

    const int b_r  = ((lid >> 4) & 1) * 8 + (lid & 7);  // within 16-row n-tile
    const unsigned b_cb = (unsigned)(((lid >> 3) & 1) * 16);

    float acc[4][4];   // [nt][frag]
    #pragma unroll
    for (int j = 0; j < 4; ++j)
        #pragma unroll
        for (int k = 0; k < 4; ++k) acc[j][k] = 0.0f;

    for (int c = 0; c < 24; ++c) {
        asm volatile("cp.async.wait_group 2;\n" ::: "memory");
        __syncthreads();

        const unsigned bchunk = stage_addr(smem_u32, c & 3);
        const int acol = a_colbase(c);

        #pragma unroll
        for (int ks = 0; ks < 4; ++ks) {
            uint32_t a[4];
            {
                int agrp = (acol >> 3) + ks * 2 + a_c8;
                unsigned g = (unsigned)(agrp ^ ax7);
                ldsm_x4(a[0], a[1], a[2], a[3], a_rowaddr + (g << 4));
            }
            uint32_t b[4][2];
            #pragma unroll
            for (int ntp = 0; ntp < 2; ++ntp) {
                unsigned off = (unsigned)((n_base + ntp * 16 + b_r) * 128)
                             + (unsigned)(ks * 32) + b_cb;
                uint32_t r0, r1, r2, r3;
                ldsm_x4(r0, r1, r2, r3, bchunk + sw128(off));
                b[ntp * 2 + 0][0] = r0; b[ntp * 2 + 0][1] = r1;
                b[ntp * 2 + 1][0] = r2; b[ntp * 2 + 1][1] = r3;
            }
            #pragma unroll
            for (int nt = 0; nt < 4; ++nt)
                mma16816(acc[nt], a, b[nt][0], b[nt][1]);
        }

        // 4 buffers, 3 in flight: writer stage (c+3)&3 != reader stage c&3,
        // and all readers of chunk c-1 passed this iteration's barrier.
        if (c + 3 < 24) load_b_chunk(smem_u32, tid, (c + 3) & 3, c + 3);
        else asm volatile("cp.async.commit_group;\n" ::: "memory");
    }

    // ---- epilogue ----
    const size_t m0 = (size_t)blockIdx.x * 64;
    const int gr = lid >> 2;
    const int gc = (lid & 3) * 2;
    #pragma unroll
    for (int nt = 0; nt < 4; ++nt) {
        const int n_ = n_base + nt * 8 + gc;
        const float b0 = bias[n_], b1 = bias[n_ + 1];
        const size_t m = m0 + (size_t)(m_base + gr);
        float2 o0; o0.x = acc[nt][0] + b0; o0.y = acc[nt][1] + b1;
        float2 o1; o1.x = acc[nt][2] + b0; o1.y = acc[nt][3] + b1;
        *(float2*)(out + m * 128 + n_)       = o0;
        *(float2*)(out + (m + 8) * 128 + n_) = o1;
    }
}

// ---------------- launch ----------------
extern "C" void kernel_launch(void* const* d_in, const int* in_sizes, int n_in,
                              void* d_out, int out_size) {
    const float* x    = (const float*)d_in[0];
    const float* U0   = (const float*)d_in[1];
    const float* W0   = (const float*)d_in[2];
    const float* Kd   = (const float*)d_in[3];
    const float* bias = (const float*)d_in[4];
    float* o = (float*)d_out;

    cudaFuncSetAttribute(fused_kernel,
                         cudaFuncAttributeMaxDynamicSharedMemorySize, SMEM_FUSE);

    kprep_kernel<<<512, 256>>>(Kd);
    fused_kernel<<<2048, NT, SMEM_FUSE>>>(x, U0, W0, bias, o);
}

// round 11
// speedup vs baseline: 1.4938x; 1.0251x over previous
#include <cuda_runtime.h>
#include <cuda_bf16.h>
#include <cstdint>

// TangentInvariant — fused single-pass, 512 threads, K-split GEMM.
//  kernel 1 (kprep): split/transpose dense_kernel -> g_kt [128][1024] bf16 (Kh|Kl)
//  kernel 2 (fused): per 64-token block:
//     phase 1: sphere-log + VN + Gram -> split bf16 y tile in SMEM [64][1024]
//     phase 2: HMMA GEMM  out[64,128] = yh*Kh + yl*Kh + yh*Kl  (fp32 acc)
//     warp layout 2(Kgroup) x 2(M) x 4(N), warp tile 32x32; K-group partials
//     reduced through smem at the end.

#define NT 512

extern __shared__ char smem_raw[];

// dense_kernel transposed+split: row n in [0,128), col k in [0,1024): (Kh | Kl)
__device__ __nv_bfloat16 g_kt[128 * 1024];

// ---------------- helpers ----------------
__device__ __forceinline__ unsigned smaddr(const void* p) {
    return (unsigned)__cvta_generic_to_shared(p);
}
__device__ __forceinline__ unsigned sw128(unsigned o) { return o ^ ((o >> 3) & 0x70); }

__device__ __forceinline__ void cp16(unsigned dst, const void* src) {
    asm volatile("cp.async.cg.shared.global [%0], [%1], 16;\n" :: "r"(dst), "l"(src));
}

__device__ __forceinline__ void ldsm_x4(uint32_t& r0, uint32_t& r1,
                                        uint32_t& r2, uint32_t& r3, unsigned a) {
    asm volatile("ldmatrix.sync.aligned.m8n8.x4.shared.b16 {%0,%1,%2,%3}, [%4];"
                 : "=r"(r0), "=r"(r1), "=r"(r2), "=r"(r3) : "r"(a));
}

__device__ __forceinline__ void mma16816(float* c, const uint32_t* a,
                                         uint32_t b0, uint32_t b1) {
    asm volatile(
        "mma.sync.aligned.m16n8k16.row.col.f32.bf16.bf16.f32 "
        "{%0,%1,%2,%3}, {%4,%5,%6,%7}, {%8,%9}, {%0,%1,%2,%3};"
        : "+f"(c[0]), "+f"(c[1]), "+f"(c[2]), "+f"(c[3])
        : "r"(a[0]), "r"(a[1]), "r"(a[2]), "r"(a[3]), "r"(b0), "r"(b1));
}

// ---------------- kernel 1: transpose + split dense_kernel ----------------
__global__ void kprep_kernel(const float* __restrict__ Kd) {
    int idx = blockIdx.x * blockDim.x + threadIdx.x;   // idx = n*1024 + k
    if (idx >= 128 * 1024) return;
    int n = idx >> 10, k = idx & 1023;
    int kk = k & 511;
    float v = (kk < 496) ? Kd[kk * 128 + n] : 0.0f;
    __nv_bfloat16 hi = __float2bfloat16(v);
    if (k < 512) g_kt[idx] = hi;
    else         g_kt[idx] = __float2bfloat16(v - __bfloat162float(hi));
}

// ---------------- fused kernel ----------------
// SMEM layout (bytes):
//   [0, 131072)          ysm  : y split bf16, token-major rows of 2048 B,
//                               element (t,f) at t*2048 + (((f>>3)^(t&7))<<4) + (f&7)*2
//   [131072, 163840)     B stages 0,1 (16 KB each); reused as the 32 KB fp32
//                        K-group reduction buffer in the epilogue
//   [163840, 228480)     phase-1 scratch (16160 floats); after phase 1 the
//                        first 32 KB are reused as B stages 2,3.
static constexpr int YSM_OFF   = 0;
static constexpr int BBUF_OFF  = 131072;
static constexpr int P1_OFF    = 163840;
static constexpr int SMEM_FUSE = 228480;

// pass structure: 24 K-chunks of 64
//   c in [0,8):   A = yh cols c*64          B = Kh cols c*64
//   c in [8,16):  A = yl cols 512+(c-8)*64  B = Kh cols (c-8)*64
//   c in [16,24): A = yh cols (c-16)*64     B = Kl cols 512+(c-16)*64
__device__ __forceinline__ int a_colbase(int c) {
    return (c < 8) ? c * 64 : (c < 16 ? 512 + (c - 8) * 64 : (c - 16) * 64);
}
__device__ __forceinline__ int b_colbase(int c) {
    return (c < 16) ? (c & 7) * 64 : 512 + (c - 16) * 64;
}
__device__ __forceinline__ unsigned stage_addr(unsigned smem_u32, int s) {
    return (s < 2) ? smem_u32 + BBUF_OFF + s * 16384
                   : smem_u32 + P1_OFF + (s - 2) * 16384;
}

__device__ __forceinline__ void load_b_chunk(unsigned smem_u32, int tid, int stage, int c) {
    const unsigned dst = stage_addr(smem_u32, stage);
    const int bc = b_colbase(c);
    #pragma unroll
    for (int it = 0; it < 2; ++it) {
        int g = tid + it * NT;          // 0..1023
        int row = g >> 3, seg = g & 7;  // 128 rows x 8 x 16B
        unsigned off = sw128((unsigned)(row * 128 + seg * 16));
        cp16(dst + off, g_kt + (size_t)row * 1024 + bc + seg * 8);
    }
    asm volatile("cp.async.commit_group;\n" ::: "memory");
}

__global__ __launch_bounds__(NT, 1)
void fused_kernel(const float* __restrict__ x,
                  const float* __restrict__ U0,
                  const float* __restrict__ W0,
                  const float* __restrict__ bias,
                  float* __restrict__ out)
{
    const unsigned smem_u32 = smaddr(smem_raw);
    const unsigned ybase = smem_u32 + YSM_OFF;
    const int tid = threadIdx.x;

    // ---- kick off B prefetch for chunks 0,1 (stages 0,1 — disjoint from p1 scratch) ----
    load_b_chunk(smem_u32, tid, 0, 0);
    load_b_chunk(smem_u32, tid, 1, 1);

    // ================= phase 1 =================
    {
        float* sm  = (float*)(smem_raw + P1_OFF);
        float* xs  = sm;           // 64*96
        float* vsm = sm + 6144;    // 64*93
        float* wsm = sm + 12096;   // 64*48
        float* Usm = sm + 15168;   // 496
        float* Wsm = sm + 15664;   // 496

        {
            const float4* src = (const float4*)(x + (size_t)blockIdx.x * (64 * 96));
            float4* dst = (float4*)xs;
            for (int g = tid; g < 1536; g += NT) dst[g] = src[g];
            for (int g = tid; g < 496; g += NT) { Usm[g] = U0[g]; Wsm[g] = W0[g]; }
        }
        __syncthreads();

        // sphere log -> v
        for (int idx = tid; idx < 64 * 31; idx += NT) {
            int t = idx / 31;
            int j = idx - t * 31;
            const float* xt = xs + t * 96;
            float px = xt[0], py = xt[1], pz = xt[2];
            const float* q = xt + 3 + j * 3;
            float qx = q[0], qy = q[1], qz = q[2];
            float cs = px * qx + py * qy + pz * qz;
            cs = fminf(1.0f, fmaxf(-1.0f, cs));
            float th = acosf(cs);
            float fac = (th < 1e-6f) ? 1.0f : th / sinf(th);
            float* vo = vsm + t * 93 + j * 3;
            vo[0] = fac * (qx - cs * px);
            vo[1] = fac * (qy - cs * py);
            vo[2] = fac * (qz - cs * pz);
        }
        __syncthreads();

        // VN layer -> w
        for (int idx = tid; idx < 64 * 16; idx += NT) {
            int t = idx >> 4;
            int i = idx & 15;
            const float* vb = vsm + t * 93;
            const float* Ur = Usm + i * 31;
            const float* Wr = Wsm + i * 31;
            float kx = 0.f, ky = 0.f, kz = 0.f, qx = 0.f, qy = 0.f, qz = 0.f;
            #pragma unroll
            for (int j = 0; j < 31; ++j) {
                float u = Ur[j], w_ = Wr[j];
                float vx = vb[j * 3 + 0], vy = vb[j * 3 + 1], vz = vb[j * 3 + 2];
                kx += u * vx;  ky += u * vy;  kz += u * vz;
                qx += w_ * vx; qy += w_ * vy; qz += w_ * vz;
            }
            float sq = kx * kx + ky * ky + kz * kz + 2.2204460492503131e-16f;
            float dt = qx * kx + qy * ky + qz * kz;
            float r = 0.8f * fmaxf(-dt, 0.0f) / sq;
            float* wo = wsm + t * 48 + i * 3;
            wo[0] = qx + r * kx;
            wo[1] = qy + r * ky;
            wo[2] = qz + r * kz;
        }
        __syncthreads();

        // Gram -> split bf16 into ysm (2 features per iter, paired 4B stores)
        for (int idx = tid; idx < 64 * 256; idx += NT) {
            int t = idx >> 8;
            int fp = (idx & 255) * 2;
            float y0 = 0.0f, y1 = 0.0f;
            if (fp < 496) {
                const float* vv = vsm + t * 93 + (fp >> 4) * 3;
                const float* w0 = wsm + t * 48 + (fp & 15) * 3;
                y0 = vv[0] * w0[0] + vv[1] * w0[1] + vv[2] * w0[2];
                int f1 = fp + 1;
                const float* vv1 = vsm + t * 93 + (f1 >> 4) * 3;
                const float* w1 = wsm + t * 48 + (f1 & 15) * 3;
                y1 = vv1[0] * w1[0] + vv1[1] * w1[1] + vv1[2] * w1[2];
            }
            __nv_bfloat16 h0 = __float2bfloat16(y0);
            __nv_bfloat16 h1 = __float2bfloat16(y1);
            __nv_bfloat16 l0 = __float2bfloat16(y0 - __bfloat162float(h0));
            __nv_bfloat16 l1 = __float2bfloat16(y1 - __bfloat162float(h1));
            const int x7 = t & 7;
            unsigned ga = (unsigned)((fp >> 3) ^ x7);
            unsigned ah = ybase + (unsigned)t * 2048 + (ga << 4) + (unsigned)(fp & 7) * 2;
            unsigned gb = (unsigned)(((512 + fp) >> 3) ^ x7);
            unsigned al = ybase + (unsigned)t * 2048 + (gb << 4) + (unsigned)(fp & 7) * 2;
            unsigned hv = ((unsigned)*(uint16_t*)&h1 << 16) | *(uint16_t*)&h0;
            unsigned lv = ((unsigned)*(uint16_t*)&l1 << 16) | *(uint16_t*)&l0;
            asm volatile("st.shared.b32 [%0], %1;" :: "r"(ah), "r"(hv) : "memory");
            asm volatile("st.shared.b32 [%0], %1;" :: "r"(al), "r"(lv) : "memory");
        }
    }
    __syncthreads();   // phase-1 scratch now dead; stages 2,3 may overwrite it

    // prefetch chunk 2 into stage 2 (overlays dead scratch)
    load_b_chunk(smem_u32, tid, 2, 2);

    // ================= phase 2: GEMM 64x128x1536, K-split x2 =================
    const int wid = tid >> 5;
    const int lid = tid & 31;
    // warp layout: kg (2) x m_w (2) x n_w (4); warp tile 32(M) x 32(N)
    const int kg     = wid >> 3;
    const int m_base = ((wid >> 2) & 1) * 32;
    const int n_base = (wid & 3) * 32;

    const int a_r  = m_base + ((lid >> 3) & 1) * 8 + (lid & 7);
    const int a_c8 = (lid >> 4) & 1;            // +8 elems in k
    const int ax7  = a_r & 7;
    const unsigned a_rowaddr = ybase + (unsigned)a_r * 2048;

    const int b_r  = ((lid >> 4) & 1) * 8 + (lid & 7);  // within 16-row n-tile
    const unsigned b_cb = (unsigned)(((lid >> 3) & 1) * 16);

    float acc[2][4][4];   // [mt][nt][frag]
    #pragma unroll
    for (int i = 0; i < 2; ++i)
        #pragma unroll
        for (int j = 0; j < 4; ++j)
            #pragma unroll
            for (int k = 0; k < 4; ++k) acc[i][j][k] = 0.0f;

    for (int c = 0; c < 24; ++c) {
        asm volatile("cp.async.wait_group 2;\n" ::: "memory");
        __syncthreads();

        if ((c & 1) == kg) {
            const unsigned bchunk = stage_addr(smem_u32, c & 3);
            const int acol = a_colbase(c);

            #pragma unroll
            for (int ks = 0; ks < 4; ++ks) {
                uint32_t a[2][4];
                {
                    int agrp = (acol >> 3) + ks * 2 + a_c8;
                    unsigned g = (unsigned)(agrp ^ ax7);
                    unsigned ad0 = a_rowaddr + (g << 4);
                    ldsm_x4(a[0][0], a[0][1], a[0][2], a[0][3], ad0);
                    ldsm_x4(a[1][0], a[1][1], a[1][2], a[1][3], ad0 + 16 * 2048);
                }
                uint32_t b[4][2];
                #pragma unroll
                for (int ntp = 0; ntp < 2; ++ntp) {
                    unsigned off = (unsigned)((n_base + ntp * 16 + b_r) * 128)
                                 + (unsigned)(ks * 32) + b_cb;
                    uint32_t r0, r1, r2, r3;
                    ldsm_x4(r0, r1, r2, r3, bchunk + sw128(off));
                    b[ntp * 2 + 0][0] = r0; b[ntp * 2 + 0][1] = r1;
                    b[ntp * 2 + 1][0] = r2; b[ntp * 2 + 1][1] = r3;
                }
                #pragma unroll
                for (int mt = 0; mt < 2; ++mt)
                    #pragma unroll
                    for (int nt = 0; nt < 4; ++nt)
                        mma16816(acc[mt][nt], a[mt], b[nt][0], b[nt][1]);
            }
        }

        // 4 buffers, 3 in flight: writer stage (c+3)&3 != any active reader.
        if (c + 3 < 24) load_b_chunk(smem_u32, tid, (c + 3) & 3, c + 3);
        else asm volatile("cp.async.commit_group;\n" ::: "memory");
    }

    // ---- epilogue: reduce the two K-groups through smem, add bias, store ----
    __syncthreads();   // all stage buffers dead now
    float* red = (float*)(smem_raw + BBUF_OFF);   // 64 x 128 fp32 = 32 KB
    const int gr = lid >> 2;
    const int gc = (lid & 3) * 2;

    if (kg == 1) {
        #pragma unroll
        for (int mt = 0; mt < 2; ++mt)
            #pragma unroll
            for (int nt = 0; nt < 4; ++nt) {
                const int r0 = m_base + mt * 16 + gr;
                const int n_ = n_base + nt * 8 + gc;
                *(float2*)(red + r0 * 128 + n_)       = make_float2(acc[mt][nt][0], acc[mt][nt][1]);
                *(float2*)(red + (r0 + 8) * 128 + n_) = make_float2(acc[mt][nt][2], acc[mt][nt][3]);
            }
    }
    __syncthreads();

    if (kg == 0) {
        const size_t m0 = (size_t)blockIdx.x * 64;
        #pragma unroll
        for (int nt = 0; nt < 4; ++nt) {
            const int n_ = n_base + nt * 8 + gc;
            const float b0 = bias[n_], b1 = bias[n_ + 1];
            #pragma unroll
            for (int mt = 0; mt < 2; ++mt) {
                const int r0 = m_base + mt * 16 + gr;
                float2 p0 = *(const float2*)(red + r0 * 128 + n_);
                float2 p1 = *(const float2*)(red + (r0 + 8) * 128 + n_);
                float2 o0, o1;
                o0.x = acc[mt][nt][0] + p0.x + b0; o0.y = acc[mt][nt][1] + p0.y + b1;
                o1.x = acc[mt][nt][2] + p1.x + b0; o1.y = acc[mt][nt][3] + p1.y + b1;
                *(float2*)(out + (m0 + r0) * 128 + n_)       = o0;
                *(float2*)(out + (m0 + r0 + 8) * 128 + n_)   = o1;
            }
        }
    }
}

// ---------------- launch ----------------
extern "C" void kernel_launch(void* const* d_in, const int* in_sizes, int n_in,
                              void* d_out, int out_size) {
    const float* x    = (const float*)d_in[0];
    const float* U0   = (const float*)d_in[1];
    const float* W0   = (const float*)d_in[2];
    const float* Kd   = (const float*)d_in[3];
    const float* bias = (const float*)d_in[4];
    float* o = (float*)d_out;

    cudaFuncSetAttribute(fused_kernel,
                         cudaFuncAttributeMaxDynamicSharedMemorySize, SMEM_FUSE);

    kprep_kernel<<<512, 256>>>(Kd);
    fused_kernel<<<2048, NT, SMEM_FUSE>>>(x, U0, W0, bias, o);
}